// round 17
// baseline (speedup 1.0000x reference)
#include <cuda_runtime.h>
#include <math.h>

#define TT 256
#define BB 512
#define DD 64
#define G3 300
#define ST 68
#define DS 104
#define NCTA 128
#define NTHR 960
#define MAXOPS 4096
#define NSWEEP 254
#define SMF 58044            // 232,176 B dynamic smem

// smem float offsets
#define O_SXA 49500
#define O_SXB 49772
#define O_SDP 50044
#define O_SH  50844
#define O_SHB 51244
#define O_SGS 51644
#define O_SGN 56444
#define O_SD  51644          // alias over sgS (DEC-only phases)
#define O_SGU 30000          // sweep-only: 6x1200 U-partials (inside sW region)
#define O_GX  37200          // sweep-only: staged gx (1200)

__device__ float g_state[(size_t)TT * BB * ST];
__device__ float g_dict[(size_t)(TT + 1) * BB * DS];
__device__ float g_xT[(size_t)TT * 65 * BB];            // [t][k][b]
__device__ float g_gx[(size_t)NCTA * NSWEEP * 1200];    // [cta][t-2][c*4+b]
__device__ int4  g_prog[MAXOPS];
__device__ int   g_nops;
__device__ float g_decWt[4 * 50 * 200];
__device__ float g_meanWt[4 * 64 * 52];

typedef unsigned long long u64;
__device__ __forceinline__ u64 pk2(float a, float b) {
    u64 r; asm("mov.b64 %0,{%1,%2};" : "=l"(r) : "f"(a), "f"(b)); return r;
}
__device__ __forceinline__ u64 ff2(u64 a, u64 b, u64 c) {
    u64 d; asm("fma.rn.f32x2 %0,%1,%2,%3;" : "=l"(d) : "l"(a), "l"(b), "l"(c)); return d;
}
__device__ __forceinline__ float sigm(float v) { return 1.f / (1.f + expf(-v)); }

__global__ void k_build(const float* __restrict__ a) {
    size_t i = (size_t)blockIdx.x * blockDim.x + threadIdx.x;
    const size_t n_state = (size_t)TT * BB * ST;
    const size_t n_dict = (size_t)BB * DS;
    if (i < n_state) {
        int t = (int)(i % TT);
        size_t r = i / TT;
        int c = (int)(r % ST);
        int b = (int)(r / ST);
        float v = 0.f;
        if (c < DD)       v = a[(((size_t)b * DD + c) * TT + t) * 3];
        else if (c == DD) v = a[(((size_t)b * DD) * TT + t) * 3 + 2];
        g_state[((size_t)t * BB + b) * ST + c] = v;
    } else if (i < n_state + n_dict) {
        g_dict[(size_t)TT * BB * DS + (i - n_state)] = 0.f;
    } else if (i < n_state + n_dict + (size_t)TT * 65 * BB) {
        size_t m = i - n_state - n_dict;
        int b = (int)(m % BB);
        size_t q = m / BB;
        int k = (int)(q % 65);
        int t = (int)(q / 65);
        float v = (k < DD) ? a[(((size_t)b * DD + k) * TT + t) * 3]
                           : a[(((size_t)b * DD) * TT + t) * 3 + 2];
        g_xT[((size_t)t * 65 + k) * BB + b] = v;
    }
}

__global__ void k_prep(const float* __restrict__ dec_W, const float* __restrict__ mean_W) {
    int i = blockIdx.x * blockDim.x + threadIdx.x;
    if (i < 40000) {
        int lvl = i / 10000, r = i % 10000, j = r / 200, k = r % 200;
        g_decWt[i] = dec_W[lvl * 10000 + k * 50 + j];
    } else if (i < 40000 + 13312) {
        int m = i - 40000;
        int lvl = m / 3328, r = m % 3328, j = r / 52, k = r % 52;
        g_meanWt[m] = (k < 50) ? mean_W[lvl * 3200 + k * 64 + j] : 0.f;
    }
}

__global__ void k_sched(const float* __restrict__ a) {
    __shared__ unsigned char obs[TT];
    int t = threadIdx.x;
    if (t < TT) obs[t] = (a[(size_t)t * 3 + 2] > 0.5f) ? 1 : 0;
    __syncthreads();
    if (t != 0) return;
    int n = 0;
    for (int k = TT - 1; k >= 2; --k) g_prog[n++] = make_int4(0, k, k, 0);
    g_prog[n++] = make_int4(1, 0, 0, 0);
    int curr = 0;
    while (curr < TT - 1) {
        if (obs[curr + 1]) {
            ++curr;
            g_prog[n++] = make_int4(1, curr, 0, 0);
        } else {
            int next_p = curr + 1;
            while (next_p < TT && !obs[next_p]) ++next_p;
            int step = 1;
            while (curr + 2 * step <= next_p && step <= 8) step *= 2;
            if (step > 1) step /= 2;
            int lvl = 0; { int s = step; while (s > 1) { s >>= 1; ++lvl; } }
            int mid = curr + step;
            g_prog[n++] = make_int4(2, mid, curr + 2 * step, lvl);
            if (step > 1) {
                int right = mid, left = curr + step / 2;
                g_prog[n++] = make_int4(0, right, right, 0);
                for (int i2 = right - 1; i2 >= left; --i2)
                    g_prog[n++] = make_int4(0, -1, i2, 0);
            }
            obs[mid] = 1;
        }
    }
    g_nops = n;
}

__global__ void __launch_bounds__(NTHR, 1) k_exec(
    const float* __restrict__ gru_W,  const float* __restrict__ gru_U,  const float* __restrict__ gru_b,
    const float* __restrict__ bgru_W, const float* __restrict__ bgru_U, const float* __restrict__ bgru_b,
    const float* __restrict__ dec_b,  const float* __restrict__ mean_b)
{
    extern __shared__ float sm[];
    float* sW  = sm;
    float* sxA = sm + O_SXA;
    float* sxB = sm + O_SXB;
    float* sdp = sm + O_SDP;
    float* sh  = sm + O_SH;
    float* shb = sm + O_SHB;
    float* sgS = sm + O_SGS;
    float* sgN = sm + O_SGN;
    float* sd  = sm + O_SD;
    float* sgU = sm + O_SGU;
    float* sgx1 = sm + O_GX;
    const int tid = threadIdx.x;
    const int b0 = blockIdx.x * 4;

    // P0: bgru_W -> smem (for gx pre-phase)
    for (int i = tid; i < 65 * G3; i += NTHR) sW[i] = bgru_W[i];
    __syncthreads();

    // P1: gx pre-phase -> global  (gx[t][c][b] = bgru_b[0] + x[t]@bgru_W)
    for (int task = tid; task < NSWEEP * 150; task += NTHR) {
        const int tt = 2 + task / 150;
        const int p = task - (task / 150) * 150;
        const int c0 = p * 2;
        float bf0 = __ldg(&bgru_b[c0]), bf1 = __ldg(&bgru_b[c0 + 1]);
        u64 a0a = pk2(bf0, bf0), a0b = a0a, a1a = pk2(bf1, bf1), a1b = a1a;
        const float2* W = (const float2*)(sW + c0);
        #pragma unroll 5
        for (int k = 0; k < 65; ++k) {
            float2 w = W[(size_t)k * 150];
            ulonglong2 x2 = *(const ulonglong2*)(g_xT + ((size_t)tt * 65 + k) * BB + b0);
            u64 w0 = pk2(w.x, w.x), w1 = pk2(w.y, w.y);
            a0a = ff2(w0, x2.x, a0a); a0b = ff2(w0, x2.y, a0b);
            a1a = ff2(w1, x2.x, a1a); a1b = ff2(w1, x2.y, a1b);
        }
        ulonglong2* dst = (ulonglong2*)(g_gx + ((size_t)blockIdx.x * NSWEEP + (tt - 2)) * 1200 + c0 * 4);
        dst[0] = make_ulonglong2(a0a, a0b);
        dst[1] = make_ulonglong2(a1a, a1b);
    }
    __syncthreads();

    // P2: bgru_U -> smem; zero h
    for (int i = tid; i < 100 * G3; i += NTHR) sW[i] = bgru_U[i];
    for (int i = tid; i < 400; i += NTHR) sh[i] = 0.f;
    __syncthreads();

    const int nops = g_nops;
    int hb_valid = -1;

    // P3: backward sweep (U-only, 6-way split over all threads, gx staged)
    for (int opi = 0; opi < NSWEEP; ++opi) {
        const int4 op = g_prog[opi];
        const int t = op.y;
        if (hb_valid != t + 1) {
            for (int i = tid; i < 400; i += NTHR)
                shb[i] = g_dict[((size_t)(t + 1) * BB + b0 + (i & 3)) * DS + (i >> 2)];
            __syncthreads();
        }
        {
            const int s6 = tid / 160, slot = tid - s6 * 160;
            if (slot < 150) {
                const int c0 = slot * 2;
                u64 h0a, h0b, h1a, h1b;
                if (s6 == 0) {
                    float bh0 = __ldg(&bgru_b[G3 + c0]), bh1 = __ldg(&bgru_b[G3 + c0 + 1]);
                    h0a = pk2(bh0, bh0); h0b = h0a; h1a = pk2(bh1, bh1); h1b = h1a;
                } else { h0a = h0b = h1a = h1b = 0ull; }
                const ulonglong2* hv = (const ulonglong2*)shb;
                const float2* U = (const float2*)(sW + c0);
                const int klo = (s6 * 100) / 6, khi = ((s6 + 1) * 100) / 6;
                #pragma unroll 6
                for (int k = klo; k < khi; ++k) {
                    float2 u = U[(size_t)k * 150];
                    ulonglong2 h2 = hv[k];
                    u64 u0 = pk2(u.x, u.x), u1 = pk2(u.y, u.y);
                    h0a = ff2(u0, h2.x, h0a); h0b = ff2(u0, h2.y, h0b);
                    h1a = ff2(u1, h2.x, h1a); h1b = ff2(u1, h2.y, h1b);
                }
                ulonglong2* o = (ulonglong2*)(sgU + s6 * 1200 + c0 * 4);
                o[0] = make_ulonglong2(h0a, h0b);
                o[1] = make_ulonglong2(h1a, h1b);
            } else {
                const int sidx = s6 * 10 + (slot - 150);
                const float* src = g_gx + ((size_t)blockIdx.x * NSWEEP + (t - 2)) * 1200;
                for (int i = sidx; i < 1200; i += 60) sgx1[i] = __ldg(&src[i]);
            }
        }
        __syncthreads();
        if (tid < 400) {
            const int j = tid >> 2, b = tid & 3;
            float Hz = 0.f, Hr = 0.f, Hn = 0.f;
            #pragma unroll
            for (int s = 0; s < 6; ++s) {
                Hz += sgU[s * 1200 + j * 4 + b];
                Hr += sgU[s * 1200 + (j + 100) * 4 + b];
                Hn += sgU[s * 1200 + (j + 200) * 4 + b];
            }
            float z  = sigm(sgx1[j * 4 + b] + Hz);
            float r  = sigm(sgx1[(j + 100) * 4 + b] + Hr);
            float nn = tanhf(sgx1[(j + 200) * 4 + b] + r * Hn);
            float hnew = z * shb[tid] + (1.f - z) * nn;
            shb[tid] = hnew;
            g_dict[((size_t)t * BB + b0 + b) * DS + j] = hnew;
        }
        hb_valid = t;
        __syncthreads();
    }

    // P4: swap smem weights -> forward GRU (W 64x300 @0, U 100x300 @19200)
    for (int i = tid; i < 64 * G3; i += NTHR)  sW[i] = gru_W[i];
    for (int i = tid; i < 100 * G3; i += NTHR) sW[19200 + i] = gru_U[i];
    __syncthreads();

    // P5: fill phase
    bool prestaged = false;
    for (int opi = NSWEEP; opi < nops; ++opi) {
        const int4 op = g_prog[opi];
        if (op.x == 2) {
            // ---- DEC ----
            const int mid = op.y, hbi = op.z, lvl = op.w;
            if (hb_valid != hbi) {
                for (int i = tid; i < 400; i += NTHR)
                    shb[i] = g_dict[((size_t)hbi * BB + b0 + (i & 3)) * DS + (i >> 2)];
                hb_valid = hbi;
            }
            __syncthreads();
            if (tid < 800) {
                const int dhalf = tid / 200, dj = (tid % 200) >> 2, db = tid & 3;
                float acc = (dhalf == 0) ? __ldg(&dec_b[lvl * 50 + dj]) : 0.f;
                const float2* dw2 = (const float2*)(g_decWt + (size_t)lvl * 10000 + dj * 200 + dhalf * 50);
                const float* src = (dhalf < 2) ? sh : shb;
                const int lb = (dhalf & 1) * 50;
                #pragma unroll 5
                for (int q = 0; q < 25; ++q) {
                    float2 w2 = __ldg(&dw2[q]);
                    int k = lb + q * 2;
                    acc += w2.x * src[k * 4 + db] + w2.y * src[(k + 1) * 4 + db];
                }
                sdp[dhalf * 200 + dj * 4 + db] = acc;
            }
            __syncthreads();
            if (tid < 200) sd[tid] = fmaxf(sdp[tid] + sdp[200 + tid] + sdp[400 + tid] + sdp[600 + tid], 0.f);
            else if (tid < 208) sd[tid] = 0.f;
            __syncthreads();
            if (tid < 256) {
                const int mj = tid >> 2, mb = tid & 3;
                float acc = __ldg(&mean_b[lvl * DD + mj]);
                const float4* mwr = (const float4*)(g_meanWt + (size_t)lvl * 3328 + mj * 52);
                #pragma unroll 4
                for (int q = 0; q < 13; ++q) {
                    float4 w4 = __ldg(&mwr[q]);
                    int k = q * 4;
                    acc += w4.x * sd[k * 4 + mb] + w4.y * sd[(k + 1) * 4 + mb]
                         + w4.z * sd[(k + 2) * 4 + mb] + w4.w * sd[(k + 3) * 4 + mb];
                }
                float* dst = &g_state[((size_t)mid * BB + b0 + mb) * ST];
                dst[mj] = acc;
                if (mj == 0) dst[DD] = 1.f;
            }
            __syncthreads();
            prestaged = false;
        } else {
            // ---- GRU (FWD: smem weights / BACK: global bgru weights) ----
            const bool fwd = (op.x == 1);
            const int t = op.y, dst = op.z;
            const bool hasx = (t >= 0);
            const int ID = fwd ? 64 : 65;
            float* sxr = (opi & 1) ? sxB : sxA;
            bool needbar = false;
            if (hasx && !prestaged) {
                const int off = fwd ? 1 : 0;
                for (int i = tid; i < ID * 4; i += NTHR)
                    sxr[(i >> 2) * 4 + (i & 3)] =
                        g_state[((size_t)t * BB + b0 + (i & 3)) * ST + (i >> 2) + off];
                needbar = true;
            }
            if (!fwd && hb_valid != dst + 1) {
                for (int i = tid; i < 400; i += NTHR)
                    shb[i] = g_dict[((size_t)(dst + 1) * BB + b0 + (i & 3)) * DS + (i >> 2)];
                needbar = true;
            }
            if (!fwd) hb_valid = dst + 1;
            if (needbar) __syncthreads();
            float* hcur = fwd ? sh : shb;
            if (tid < 640) {
                const int gs = tid / 160, slot = tid - gs * 160;
                if (slot < 150) {
                    const int c0 = slot * 2;
                    u64 ax0a, ax0b, ax1a, ax1b, ah0a, ah0b, ah1a, ah1b;
                    if (gs == 0) {
                        const float* bias = fwd ? gru_b : bgru_b;
                        float bx0 = __ldg(&bias[c0]),      bx1 = __ldg(&bias[c0 + 1]);
                        float bh0 = __ldg(&bias[G3 + c0]), bh1 = __ldg(&bias[G3 + c0 + 1]);
                        ax0a = pk2(bx0, bx0); ax0b = ax0a; ax1a = pk2(bx1, bx1); ax1b = ax1a;
                        ah0a = pk2(bh0, bh0); ah0b = ah0a; ah1a = pk2(bh1, bh1); ah1b = ah1a;
                    } else {
                        ax0a = ax0b = ax1a = ax1b = 0ull;
                        ah0a = ah0b = ah1a = ah1b = 0ull;
                    }
                    const ulonglong2* xv = (const ulonglong2*)sxr;
                    const ulonglong2* hv = (const ulonglong2*)hcur;
                    if (hasx) {
                        const int klo = (gs * ID) >> 2, khi = ((gs + 1) * ID) >> 2;
                        const int khiF = (gs == 3) ? ID : khi;
                        const float2* W = fwd ? (const float2*)(sW + c0)
                                              : (const float2*)(bgru_W + c0);
                        #pragma unroll 8
                        for (int k = klo; k < khiF; ++k) {
                            float2 w = fwd ? W[(size_t)k * 150] : __ldg(&W[(size_t)k * 150]);
                            ulonglong2 x2 = xv[k];
                            u64 w0 = pk2(w.x, w.x), w1 = pk2(w.y, w.y);
                            ax0a = ff2(w0, x2.x, ax0a); ax0b = ff2(w0, x2.y, ax0b);
                            ax1a = ff2(w1, x2.x, ax1a); ax1b = ff2(w1, x2.y, ax1b);
                        }
                    }
                    const int ulo = gs * 25, uhi = ulo + 25;
                    const float2* U = fwd ? (const float2*)(sW + 19200 + c0)
                                          : (const float2*)(bgru_U + c0);
                    #pragma unroll 8
                    for (int k = ulo; k < uhi; ++k) {
                        float2 u = fwd ? U[(size_t)k * 150] : __ldg(&U[(size_t)k * 150]);
                        ulonglong2 h2 = hv[k];
                        u64 u0 = pk2(u.x, u.x), u1 = pk2(u.y, u.y);
                        ah0a = ff2(u0, h2.x, ah0a); ah0b = ff2(u0, h2.y, ah0b);
                        ah1a = ff2(u1, h2.x, ah1a); ah1b = ff2(u1, h2.y, ah1b);
                    }
                    ulonglong2* outS = (ulonglong2*)(sgS + gs * 1200 + c0 * 4);
                    if (c0 < 200) {
                        u64 s0a, s0b, s1a, s1b;
                        asm("add.rn.f32x2 %0,%1,%2;" : "=l"(s0a) : "l"(ax0a), "l"(ah0a));
                        asm("add.rn.f32x2 %0,%1,%2;" : "=l"(s0b) : "l"(ax0b), "l"(ah0b));
                        asm("add.rn.f32x2 %0,%1,%2;" : "=l"(s1a) : "l"(ax1a), "l"(ah1a));
                        asm("add.rn.f32x2 %0,%1,%2;" : "=l"(s1b) : "l"(ax1b), "l"(ah1b));
                        outS[0] = make_ulonglong2(s0a, s0b);
                        outS[1] = make_ulonglong2(s1a, s1b);
                    } else {
                        outS[0] = make_ulonglong2(ax0a, ax0b);
                        outS[1] = make_ulonglong2(ax1a, ax1b);
                        ulonglong2* outN = (ulonglong2*)(sgN + gs * 400 + (c0 - 200) * 4);
                        outN[0] = make_ulonglong2(ah0a, ah0b);
                        outN[1] = make_ulonglong2(ah1a, ah1b);
                    }
                }
            } else if (opi + 1 < nops) {
                // stage threads: prefetch next op's x
                const int4 nx = g_prog[opi + 1];
                if (nx.x != 2 && nx.y >= 0) {
                    const int nID = (nx.x == 1) ? 64 : 65;
                    const int noff = (nx.x == 1) ? 1 : 0;
                    float* sxw = ((opi + 1) & 1) ? sxB : sxA;
                    for (int i = tid - 640; i < nID * 4; i += 320)
                        sxw[(i >> 2) * 4 + (i & 3)] =
                            g_state[((size_t)nx.y * BB + b0 + (i & 3)) * ST + (i >> 2) + noff];
                }
            }
            __syncthreads();
            if (tid < 400) {
                const int j = tid >> 2, b = tid & 3;
                float Sz = 0.f, Sr = 0.f, Xn = 0.f, Hn = 0.f;
                #pragma unroll
                for (int s = 0; s < 4; ++s) {
                    Sz += sgS[s * 1200 + j * 4 + b];
                    Sr += sgS[s * 1200 + (j + 100) * 4 + b];
                    Xn += sgS[s * 1200 + (j + 200) * 4 + b];
                    Hn += sgN[s * 400 + j * 4 + b];
                }
                float z  = sigm(Sz);
                float r  = sigm(Sr);
                float nn = tanhf(Xn + r * Hn);
                float hnew = z * hcur[tid] + (1.f - z) * nn;
                hcur[tid] = hnew;
                if (!fwd) g_dict[((size_t)dst * BB + b0 + b) * DS + j] = hnew;
            }
            if (!fwd) hb_valid = dst;
            __syncthreads();
            prestaged = true;
        }
    }
}

__global__ void k_out(float* __restrict__ out) {
    size_t i = (size_t)blockIdx.x * blockDim.x + threadIdx.x;
    if (i >= (size_t)BB * DD * TT) return;
    int t = (int)(i % TT);
    size_t r = i / TT;
    int d = (int)(r % DD);
    int b = (int)(r / DD);
    out[i] = g_state[((size_t)t * BB + b) * ST + d + 1];
}

extern "C" void kernel_launch(void* const* d_in, const int* in_sizes, int n_in,
                              void* d_out, int out_size) {
    const float* a      = (const float*)d_in[0];
    const float* gru_W  = (const float*)d_in[1];
    const float* gru_U  = (const float*)d_in[2];
    const float* gru_b  = (const float*)d_in[3];
    const float* bgru_W = (const float*)d_in[4];
    const float* bgru_U = (const float*)d_in[5];
    const float* bgru_b = (const float*)d_in[6];
    const float* dec_W  = (const float*)d_in[7];
    const float* dec_b  = (const float*)d_in[8];
    const float* mean_W = (const float*)d_in[9];
    const float* mean_b = (const float*)d_in[10];
    float* out = (float*)d_out;

    size_t nbuild = (size_t)TT * BB * ST + (size_t)BB * DS + (size_t)TT * 65 * BB;
    k_build<<<(unsigned)((nbuild + 255) / 256), 256>>>(a);
    k_prep<<<(40000 + 13312 + 255) / 256, 256>>>(dec_W, mean_W);
    k_sched<<<1, 256>>>(a);
    cudaFuncSetAttribute(k_exec, cudaFuncAttributeMaxDynamicSharedMemorySize, SMF * 4);
    k_exec<<<NCTA, NTHR, SMF * 4>>>(gru_W, gru_U, gru_b, bgru_W, bgru_U, bgru_b,
                                    dec_b, mean_b);
    size_t nout = (size_t)BB * DD * TT;
    k_out<<<(unsigned)((nout + 255) / 256), 256>>>(out);
}